// round 4
// baseline (speedup 1.0000x reference)
#include <cuda_runtime.h>
#include <cstdint>

// ShapeIndex over (B=16, C=1, H=1536, W=1536) fp32.
// si = remove_nan( (2/pi) * atan( (k_max+k_min)/(k_max-k_min) ) )
// Algebra: ratio == -N1 / sqrt(N1^2 - 4*u*N2), u = 1+p^2+q^2,
//          N1 = (1+q^2)r - 2pqs + (1+p^2)t, N2 = r*t - s^2.

#define BB 16
#define HH 1536
#define WW 1536
#define W4 (WW / 4)

// NaN -> 0 that survives fast-math (bit test, no isnan()).
__device__ __forceinline__ float remove_nan(float v) {
    unsigned u = __float_as_uint(v);
    return ((u & 0x7fffffffu) > 0x7f800000u) ? 0.0f : v;
}

__device__ __forceinline__ float shape_index(float xc, float xh1, float xh2,
                                             float xm1, float xm2, float xh1m1) {
    // p = x[h-1][w]-x[h][w]; q = x[h][w-1]-x[h][w]
    float p = xh1 - xc;
    float q = xm1 - xc;
    // r = x[h-2]-2x[h-1]+x[h] (along H); t likewise along W; s = cross
    float r = (xh2 - xh1) - (xh1 - xc);
    float t = (xm2 - xm1) - (xm1 - xc);
    float s = (xh1m1 - xm1) - (xh1 - xc);

    float p2 = p * p, q2 = q * q, pq = p * q;
    float a = 1.0f + q2;
    float b = 1.0f + p2;
    float u = a + p2;                         // 1 + p^2 + q^2
    float N1 = fmaf(a, r, fmaf(b, t, -2.0f * pq * s));
    float N2 = fmaf(r, t, -s * s);
    float D  = fmaf(N1, N1, -4.0f * u * N2);  // (2*u^1.5)^2 * (Hc^2 - Kc)
    // D<0  -> rsqrt NaN -> atan NaN -> 0   (matches root=NaN path)
    // D=0, N1!=0 -> +-inf -> atan -> +-pi/2 (matches Hc/0)
    // D=0, N1=0  -> NaN -> 0
    float ratio = -N1 * rsqrtf(D);
    float si = 0.63661977236758134308f * atanf(ratio);
    return remove_nan(si);
}

__global__ __launch_bounds__(256)
void si_kernel(const float* __restrict__ x, float* __restrict__ out) {
    int idx = blockIdx.x * blockDim.x + threadIdx.x;
    const int total = BB * HH * W4;
    if (idx >= total) return;

    int w4 = idx % W4;
    int hb = idx / W4;
    int h = hb % HH;
    // b folded into hb: image base uses hb directly since C=1 and layout is (B,H,W)
    int w0 = w4 * 4;

    const float* img_row_base = x + (size_t)(hb - h) * WW;  // start of this image
    int hm1 = (h == 0) ? HH - 1 : h - 1;
    int hm2 = (hm1 == 0) ? HH - 1 : hm1 - 1;

    const float* rowh  = img_row_base + (size_t)h   * WW;
    const float* rowh1 = img_row_base + (size_t)hm1 * WW;
    const float* rowh2 = img_row_base + (size_t)hm2 * WW;

    float4 a  = *reinterpret_cast<const float4*>(rowh  + w0);
    float4 c1 = *reinterpret_cast<const float4*>(rowh1 + w0);
    float4 c2 = *reinterpret_cast<const float4*>(rowh2 + w0);

    // boundary scalars for w0-1, w0-2 (wrap only when w0==0; w0 is a multiple of 4)
    int wm1 = (w0 == 0) ? WW - 1 : w0 - 1;
    int wm2 = (w0 == 0) ? WW - 2 : w0 - 2;
    float am1  = rowh[wm1];
    float am2  = rowh[wm2];
    float c1m1 = rowh1[wm1];

    float4 o;
    o.x = shape_index(a.x, c1.x, c2.x, am1, am2, c1m1);
    o.y = shape_index(a.y, c1.y, c2.y, a.x,  am1, c1.x);
    o.z = shape_index(a.z, c1.z, c2.z, a.y,  a.x, c1.y);
    o.w = shape_index(a.w, c1.w, c2.w, a.z,  a.y, c1.z);

    *reinterpret_cast<float4*>(out + (size_t)idx * 4) = o;
}

extern "C" void kernel_launch(void* const* d_in, const int* in_sizes, int n_in,
                              void* d_out, int out_size) {
    const float* x = (const float*)d_in[0];
    float* out = (float*)d_out;
    const int total = BB * HH * W4;          // 9,437,184 threads
    const int threads = 256;
    const int blocks = (total + threads - 1) / threads;
    si_kernel<<<blocks, threads>>>(x, out);
}

// round 5
// speedup vs baseline: 1.1166x; 1.1166x over previous
#include <cuda_runtime.h>
#include <cstdint>

// ShapeIndex over (B=16, C=1, H=1536, W=1536) fp32.
// si = remove_nan( (2/pi) * atan( (k_max+k_min)/(k_max-k_min) ) )
// Algebra: ratio = -N1 / sqrt(D),  D = N1^2 - 4*u*N2,
//          N1 = (1+q^2)r - 2pqs + (1+p^2)t, N2 = r*t - s^2, u = 1+p^2+q^2.
// atan(y/sqrt(D)) = asin(y/sqrt(D + y^2))  (denominator >= 0), so
//   si = (2/pi)*asin(t),  t = -N1 * rsqrt(2*N1^2 - 4*u*N2)    -- no division.
// asin via A&S 4.4.45 with 2/pi folded in:
//   si = sign(t) * (1 - sqrt(1-|t|) * P(|t|)),  P = 3-term poly, |err| <= 4.3e-5.

#define BB 16
#define HH 1536
#define WW 1536
#define W4 (WW / 4)

// NaN -> 0 (bit test; survives any compiler flags).
__device__ __forceinline__ float remove_nan(float v) {
    unsigned u = __float_as_uint(v);
    return ((u & 0x7fffffffu) > 0x7f800000u) ? 0.0f : v;
}

__device__ __forceinline__ float sqrt_approx(float x) {
    float r;
    asm("sqrt.approx.f32 %0, %1;" : "=f"(r) : "f"(x));
    return r;
}

__device__ __forceinline__ float shape_index(float xc, float xh1, float xh2,
                                             float xm1, float xm2, float xh1m1) {
    float p = xh1 - xc;
    float q = xm1 - xc;
    float r = (xh2 - xh1) - p;
    float t = (xm2 - xm1) - q;
    float s = (xh1m1 - xm1) - p;

    float p2 = p * p, q2 = q * q;
    float a = 1.0f + q2;
    float b = 1.0f + p2;
    float u = a + p2;                               // 1 + p^2 + q^2
    float pqs = (p * q) * s;
    float N1 = fmaf(a, r, fmaf(b, t, -2.0f * pqs));
    float N2 = fmaf(r, t, -(s * s));
    float den = fmaf(2.0f * N1, N1, -4.0f * u * N2); // N1^2 + D
    // den<0 -> NaN -> 0; den=0,N1!=0 -> D<0 -> NaN path below -> 0;
    // den>0, D<0 -> |tt|>1 -> sqrt(1-|tt|)=NaN -> 0 (matches NaN root).
    float tt = -N1 * rsqrtf(den);
    float aa = fabsf(tt);
    // (2/pi)*P(|t|): coefficients of A&S 4.4.45 scaled by 2/pi
    float poly = fmaf(fmaf(fmaf(-0.0119235f, aa, 0.0472761f),
                           aa, -0.1350363f), aa, 0.9999570f);
    float mag = fmaf(-sqrt_approx(1.0f - aa), poly, 1.0f);  // (2/pi)*asin(|t|)
    float si = copysignf(mag, tt);
    return remove_nan(si);
}

__global__ __launch_bounds__(W4)
void si_kernel(const float* __restrict__ x, float* __restrict__ out) {
    const int w4 = threadIdx.x;          // 0..383
    const int h  = blockIdx.x;           // 0..1535
    const int b  = blockIdx.y;           // 0..15
    const int w0 = w4 * 4;

    const float* img = x + (size_t)b * (HH * WW);
    const int hm1 = (h == 0) ? HH - 1 : h - 1;
    const int hm2 = (hm1 == 0) ? HH - 1 : hm1 - 1;

    const float* rowh  = img + h   * WW;
    const float* rowh1 = img + hm1 * WW;
    const float* rowh2 = img + hm2 * WW;

    float4 a  = *reinterpret_cast<const float4*>(rowh  + w0);
    float4 c1 = *reinterpret_cast<const float4*>(rowh1 + w0);
    float4 c2 = *reinterpret_cast<const float4*>(rowh2 + w0);

    // boundary scalars for w0-1, w0-2 (wrap only at w0==0)
    const int wm1 = (w0 == 0) ? WW - 1 : w0 - 1;
    const int wm2 = (w0 == 0) ? WW - 2 : w0 - 2;
    float am1  = rowh[wm1];
    float am2  = rowh[wm2];
    float c1m1 = rowh1[wm1];

    float4 o;
    o.x = shape_index(a.x, c1.x, c2.x, am1, am2, c1m1);
    o.y = shape_index(a.y, c1.y, c2.y, a.x,  am1, c1.x);
    o.z = shape_index(a.z, c1.z, c2.z, a.y,  a.x, c1.y);
    o.w = shape_index(a.w, c1.w, c2.w, a.z,  a.y, c1.z);

    float* orow = out + ((size_t)b * HH + h) * WW;
    *reinterpret_cast<float4*>(orow + w0) = o;
}

extern "C" void kernel_launch(void* const* d_in, const int* in_sizes, int n_in,
                              void* d_out, int out_size) {
    const float* x = (const float*)d_in[0];
    float* out = (float*)d_out;
    dim3 grid(HH, BB, 1);    // h, b
    si_kernel<<<grid, W4>>>(x, out);
}